// round 7
// baseline (speedup 1.0000x reference)
#include <cuda_runtime.h>
#include <cuda_bf16.h>

// RFFT-1024 over 8192 rows -> real[8192][513] ++ imag[8192][513].
// R4: four-step 32x32 register FFT (R3 resubmit; twiddle tables made
// function-local so they fold to immediates). One warp per packed complex
// FFT (2 real rows). No block barriers; single warp-private SMEM transpose.

#define NFFT    1024
#define NOUT    513
#define THREADS 128           // 4 warps -> 4 FFT pairs per block
#define WPB     (THREADS / 32)

__device__ __forceinline__ constexpr int rev5(int i) {
    return ((i & 1) << 4) | ((i & 2) << 2) | (i & 4) | ((i >> 2) & 2) | ((i >> 4) & 1);
}

// 32-point DIT FFT on registers; expects input already bit-reverse wired,
// produces natural-order output. Fully unrolled; twiddles fold to literals.
__device__ __forceinline__ void fft32_stages(float zr[32], float zi[32]) {
    // cos/sin(2*pi*q/32), q = 0..15 — local const arrays + constant indices
    // after unroll => SROA folds them into immediate operands (no LDC/LDG).
    const float COS32[16] = {
        1.00000000f,  0.98078528f,  0.92387953f,  0.83146961f,
        0.70710678f,  0.55557023f,  0.38268343f,  0.19509032f,
        0.00000000f, -0.19509032f, -0.38268343f, -0.55557023f,
       -0.70710678f, -0.83146961f, -0.92387953f, -0.98078528f };
    const float SIN32[16] = {
        0.00000000f,  0.19509032f,  0.38268343f,  0.55557023f,
        0.70710678f,  0.83146961f,  0.92387953f,  0.98078528f,
        1.00000000f,  0.98078528f,  0.92387953f,  0.83146961f,
        0.70710678f,  0.55557023f,  0.38268343f,  0.19509032f };

#pragma unroll
    for (int m = 1; m <= 5; ++m) {
        const int len = 1 << m, half = len >> 1, tstep = 32 >> m;
#pragma unroll
        for (int base = 0; base < 32; base += len) {
#pragma unroll
            for (int q = 0; q < half; ++q) {
                const float wr =  COS32[q * tstep];
                const float wi = -SIN32[q * tstep];   // W = e^{-2pi i q/len}
                const int i0 = base + q, i1 = i0 + half;
                const float tr = wr * zr[i1] - wi * zi[i1];
                const float ti = wr * zi[i1] + wi * zr[i1];
                const float ur = zr[i0], ui = zi[i0];
                zr[i0] = ur + tr;  zi[i0] = ui + ti;
                zr[i1] = ur - tr;  zi[i1] = ui - ti;
            }
        }
    }
}

__global__ void __launch_bounds__(THREADS)
rfft1024_fourstep_kernel(const float* __restrict__ x,
                         float* __restrict__ out_real,
                         float* __restrict__ out_imag)
{
    __shared__ float sbr[WPB][1056];   // 32x33 transpose buffer per warp
    __shared__ float sbi[WPB][1056];

    const int w    = threadIdx.x >> 5;
    const int j    = threadIdx.x & 31;            // lane == n2 (pass 1), k1 (pass 2)
    const int fft  = blockIdx.x * WPB + w;        // packed-FFT index (pair of rows)

    const float* __restrict__ xa = x + (size_t)(2 * fft) * NFFT;
    const float* __restrict__ xb = xa + NFFT;

    float zr[32], zi[32];

    // ---- load column n2=j (coalesced), bit-reverse wired into registers ----
#pragma unroll
    for (int n1 = 0; n1 < 32; ++n1) {
        const int r = rev5(n1);
        zr[r] = xa[32 * n1 + j];     // real <- row 2*fft
        zi[r] = xb[32 * n1 + j];     // imag <- row 2*fft+1
    }

    // ---- pass 1: FFT32 over n1 ----
    fft32_stages(zr, zi);

    // ---- twiddle: z[k1] *= W1024^{j*k1} (recurrence, refresh every 8) ----
    {
        const float a1 = (-6.28318530717958647692f / 1024.0f) * (float)j;
        float w1r, w1i;  __sincosf(a1, &w1i, &w1r);
        float wr = 1.0f, wi = 0.0f;
#pragma unroll
        for (int k1 = 0; k1 < 32; ++k1) {
            if (k1 == 8 || k1 == 16 || k1 == 24)
                __sincosf(a1 * (float)k1, &wi, &wr);
            const float zr0 = zr[k1], zi0 = zi[k1];
            zr[k1] = wr * zr0 - wi * zi0;
            zi[k1] = wr * zi0 + wi * zr0;
            const float nwr = wr * w1r - wi * w1i;
            const float nwi = wr * w1i + wi * w1r;
            wr = nwr; wi = nwi;
        }
    }

    // ---- transpose via warp-private padded SMEM (conflict-free both ways) ----
    float* __restrict__ tr_s = sbr[w];
    float* __restrict__ ti_s = sbi[w];
#pragma unroll
    for (int k1 = 0; k1 < 32; ++k1) {
        tr_s[k1 * 33 + j] = zr[k1];
        ti_s[k1 * 33 + j] = zi[k1];
    }
    __syncwarp();
#pragma unroll
    for (int n2 = 0; n2 < 32; ++n2) {
        const int r = rev5(n2);
        zr[r] = tr_s[j * 33 + n2];
        zi[r] = ti_s[j * 33 + n2];
    }

    // ---- pass 2: FFT32 over n2 -> Z[j + 32*k2] in slot k2, natural order ----
    fft32_stages(zr, zi);

    // ---- Hermitian unpack + store: Xa, Xb from Z[k], Z[N-k] ----
    const size_t rA = (size_t)(2 * fft) * NOUT;
    const size_t rB = rA + NOUT;
    const int    partner = (32 - j) & 31;
#pragma unroll
    for (int k2 = 0; k2 < 17; ++k2) {
        // Z[N-k]: lane (32-j)%32, slot 31-k2  (j>0); lane 0 self-pairs slot (32-k2)%32
        float cr = __shfl_sync(0xffffffffu, zr[31 - k2], partner);
        float ci = __shfl_sync(0xffffffffu, zi[31 - k2], partner);
        if (j == 0) { cr = zr[(32 - k2) & 31]; ci = zi[(32 - k2) & 31]; }
        const float a = zr[k2], b = zi[k2];          // Z[k]
        const int k = j + 32 * k2;
        if (k < NOUT) {
            out_real[rA + k] = 0.5f * (a + cr);      // Re Xa
            out_imag[rA + k] = 0.5f * (b - ci);      // Im Xa
            out_real[rB + k] = 0.5f * (b + ci);      // Re Xb
            out_imag[rB + k] = 0.5f * (cr - a);      // Im Xb
        }
    }
}

extern "C" void kernel_launch(void* const* d_in, const int* in_sizes, int n_in,
                              void* d_out, int out_size)
{
    const float* x = (const float*)d_in[0];
    float* out = (float*)d_out;
    const int n_rows = in_sizes[0] / NFFT;              // 8192
    float* out_real = out;
    float* out_imag = out + (size_t)n_rows * NOUT;

    const int n_pairs = n_rows / 2;                     // 4096 packed FFTs
    rfft1024_fourstep_kernel<<<n_pairs / WPB, THREADS>>>(x, out_real, out_imag);
}

// round 8
// speedup vs baseline: 3.6943x; 3.6943x over previous
#include <cuda_runtime.h>
#include <cuda_bf16.h>

// RFFT-1024 over 8192 rows -> real[8192][513] ++ imag[8192][513].
// R7: 1024 = 16 x (16 x 4). 64 threads per packed complex FFT (2 real rows),
// 16 complex points per thread. Register FFT16s via macros (straight-line,
// literal twiddles), 2 SMEM exchanges + Z scatter, 3 block barriers.

#define NFFT    1024
#define NOUT    513
#define THREADS 128            // 2 packed FFTs per block (64 threads each)

__device__ __forceinline__ constexpr int rev4(int i) {      // base-4 digit rev, 2 digits
    return ((i & 3) << 2) | ((i >> 2) & 3);
}
__device__ __forceinline__ int P6(int k) { return k + ((k >> 6) << 4); }

// radix-4 DIT butterfly with twiddles (wr,wi) = W^{k}, W^{2k}, W^{3k} (e^{-i} sign folded in)
#define R4B(zr, zi, i0, i1, i2, i3, w1r, w1i, w2r, w2i, w3r, w3i) do {          \
    float t1r = (w1r)*zr[i1] - (w1i)*zi[i1], t1i = (w1r)*zi[i1] + (w1i)*zr[i1]; \
    float t2r = (w2r)*zr[i2] - (w2i)*zi[i2], t2i = (w2r)*zi[i2] + (w2i)*zr[i2]; \
    float t3r = (w3r)*zr[i3] - (w3i)*zi[i3], t3i = (w3r)*zi[i3] + (w3i)*zr[i3]; \
    float e0r = zr[i0] + t2r, e0i = zi[i0] + t2i;                               \
    float e1r = zr[i0] - t2r, e1i = zi[i0] - t2i;                               \
    float o0r = t1r + t3r,    o0i = t1i + t3i;                                  \
    float o1r = t1r - t3r,    o1i = t1i - t3i;                                  \
    zr[i0] = e0r + o0r;  zi[i0] = e0i + o0i;                                    \
    zr[i1] = e1r + o1i;  zi[i1] = e1i - o1r;                                    \
    zr[i2] = e0r - o0r;  zi[i2] = e0i - o0i;                                    \
    zr[i3] = e1r - o1i;  zi[i3] = e1i + o1r;                                    \
} while (0)

// twiddle-free variant
#define R4B_NT(zr, zi, i0, i1, i2, i3) do {                                     \
    float e0r = zr[i0] + zr[i2], e0i = zi[i0] + zi[i2];                         \
    float e1r = zr[i0] - zr[i2], e1i = zi[i0] - zi[i2];                         \
    float o0r = zr[i1] + zr[i3], o0i = zi[i1] + zi[i3];                         \
    float o1r = zr[i1] - zr[i3], o1i = zi[i1] - zi[i3];                         \
    zr[i0] = e0r + o0r;  zi[i0] = e0i + o0i;                                    \
    zr[i1] = e1r + o1i;  zi[i1] = e1i - o1r;                                    \
    zr[i2] = e0r - o0r;  zi[i2] = e0i - o0i;                                    \
    zr[i3] = e1r - o1i;  zi[i3] = e1i + o1r;                                    \
} while (0)

// 16-point DIT FFT: input base-4 digit-reversed, output natural order.
#define FFT16(zr, zi) do {                                                      \
    R4B_NT(zr, zi,  0,  1,  2,  3);                                             \
    R4B_NT(zr, zi,  4,  5,  6,  7);                                             \
    R4B_NT(zr, zi,  8,  9, 10, 11);                                             \
    R4B_NT(zr, zi, 12, 13, 14, 15);                                             \
    R4B_NT(zr, zi,  0,  4,  8, 12);                                             \
    R4B(zr, zi, 1, 5,  9, 13,  0.92387953f,-0.38268343f,                        \
                               0.70710678f,-0.70710678f,                        \
                               0.38268343f,-0.92387953f);                       \
    R4B(zr, zi, 2, 6, 10, 14,  0.70710678f,-0.70710678f,                        \
                               0.0f,       -1.0f,                               \
                              -0.70710678f,-0.70710678f);                       \
    R4B(zr, zi, 3, 7, 11, 15,  0.38268343f,-0.92387953f,                        \
                              -0.70710678f,-0.70710678f,                        \
                              -0.92387953f, 0.38268343f);                       \
} while (0)

__global__ void __launch_bounds__(THREADS, 4)
rfft1024_r7_kernel(const float* __restrict__ x,
                   float* __restrict__ out_real,
                   float* __restrict__ out_imag)
{
    // B1: exchange-1 buffer ([k1][j] stride 66), later reused for Z (P6 pad, 1264)
    // B2: exchange-2 buffer ([n2][k1][m1] stride 17, 4*272 = 1088)
    __shared__ float B1r[2][1264], B1i[2][1264];
    __shared__ float B2r[2][1088], B2i[2][1088];

    const int f   = threadIdx.x >> 6;            // which FFT within block
    const int j   = threadIdx.x & 63;            // column index within FFT
    const int fft = blockIdx.x * 2 + f;          // packed-FFT (row pair) index

    const float* __restrict__ xa = x + (size_t)(2 * fft) * NFFT;
    const float* __restrict__ xb = xa + NFFT;

    float zr[16], zi[16];

    // ---- load z[n1] = x[64*n1 + j], bit-rev wired, packed (a + i b) ----
#pragma unroll
    for (int n1 = 0; n1 < 16; ++n1) {
        const int r = rev4(n1);
        zr[r] = xa[64 * n1 + j];
        zi[r] = xb[64 * n1 + j];
    }

    // ---- stage 1: FFT16 over n1 ----
    FFT16(zr, zi);

    // ---- twiddle W1024^{j*k1} (recurrence, refresh at k1=8) ----
    {
        const float a1 = (-6.28318530717958647692f / 1024.0f) * (float)j;
        float stepi, stepr;  __sincosf(a1, &stepi, &stepr);
        float wr = 1.0f, wi = 0.0f;
#pragma unroll
        for (int k1 = 0; k1 < 16; ++k1) {
            if (k1 == 8) __sincosf(a1 * 8.0f, &wi, &wr);
            const float tr = wr * zr[k1] - wi * zi[k1];
            const float ti = wr * zi[k1] + wi * zr[k1];
            zr[k1] = tr;  zi[k1] = ti;
            const float nr = wr * stepr - wi * stepi;
            const float ni = wr * stepi + wi * stepr;
            wr = nr;  wi = ni;
        }
    }

    // ---- exchange 1: write [k1][j] (stride 66, conflict-free) ----
#pragma unroll
    for (int k1 = 0; k1 < 16; ++k1) {
        B1r[f][k1 * 66 + j] = zr[k1];
        B1i[f][k1 * 66 + j] = zi[k1];
    }
    __syncthreads();

    // ---- read u[n1] = y^{(k1)}[4*n1 + n2]  (conflict-free) ----
    const int k1t = j & 15;
    const int n2t = j >> 4;                      // 0..3
    const int rb  = k1t * 66 + n2t;
#pragma unroll
    for (int n1 = 0; n1 < 16; ++n1) {
        const int r = rev4(n1);
        zr[r] = B1r[f][rb + 4 * n1];
        zi[r] = B1i[f][rb + 4 * n1];
    }

    // ---- stage 2a: FFT16 over n1 (length-64 sub-FFT, part 1) ----
    FFT16(zr, zi);

    // ---- twiddle W64^{n2*m1} ----
    {
        const float b1 = (-6.28318530717958647692f / 64.0f) * (float)n2t;
        float stepi, stepr;  __sincosf(b1, &stepi, &stepr);
        float wr = 1.0f, wi = 0.0f;
#pragma unroll
        for (int m1 = 0; m1 < 16; ++m1) {
            if (m1 == 8) __sincosf(b1 * 8.0f, &wi, &wr);
            const float tr = wr * zr[m1] - wi * zi[m1];
            const float ti = wr * zi[m1] + wi * zr[m1];
            zr[m1] = tr;  zi[m1] = ti;
            const float nr = wr * stepr - wi * stepi;
            const float ni = wr * stepi + wi * stepr;
            wr = nr;  wi = ni;
        }
    }

    // ---- exchange 2: write [n2][k1][m1] stride 17 (conflict-free) ----
    {
        const int wb = n2t * 272 + k1t * 17;
#pragma unroll
        for (int m1 = 0; m1 < 16; ++m1) {
            B2r[f][wb + m1] = zr[m1];
            B2i[f][wb + m1] = zi[m1];
        }
    }
    __syncthreads();

    // ---- stage 2b: DFT4 over n2 per (k1, m1); scatter Z into B1 (P6 pad) ----
    {
        const int qk1 = j & 15;
        const int qg  = j >> 4;                  // m1 group
#pragma unroll
        for (int q = 0; q < 4; ++q) {
            const int m1   = 4 * qg + q;
            const int base = qk1 * 17 + m1;
            const float q0r = B2r[f][base],       q0i = B2i[f][base];
            const float q1r = B2r[f][base + 272], q1i = B2i[f][base + 272];
            const float q2r = B2r[f][base + 544], q2i = B2i[f][base + 544];
            const float q3r = B2r[f][base + 816], q3i = B2i[f][base + 816];

            const float e0r = q0r + q2r, e0i = q0i + q2i;
            const float e1r = q0r - q2r, e1i = q0i - q2i;
            const float o0r = q1r + q3r, o0i = q1i + q3i;
            const float o1r = q1r - q3r, o1i = q1i - q3i;

            const int k0 = qk1 + 16 * m1;
            B1r[f][P6(k0)]       = e0r + o0r;  B1i[f][P6(k0)]       = e0i + o0i;
            B1r[f][P6(k0 + 256)] = e1r + o1i;  B1i[f][P6(k0 + 256)] = e1i - o1r;
            B1r[f][P6(k0 + 512)] = e0r - o0r;  B1i[f][P6(k0 + 512)] = e0i - o0i;
            B1r[f][P6(k0 + 768)] = e1r - o1i;  B1i[f][P6(k0 + 768)] = e1i + o1r;
        }
    }
    __syncthreads();

    // ---- Hermitian unpack + store ----
    const size_t rA = (size_t)(2 * fft) * NOUT;
    const size_t rB = rA + NOUT;
#pragma unroll
    for (int i = 0; i < 8; ++i) {
        const int k  = j + 64 * i;                       // 0..511
        const int nk = (NFFT - k) & (NFFT - 1);
        const float a = B1r[f][P6(k)],  b = B1i[f][P6(k)];
        const float c = B1r[f][P6(nk)], d = B1i[f][P6(nk)];
        out_real[rA + k] = 0.5f * (a + c);
        out_imag[rA + k] = 0.5f * (b - d);
        out_real[rB + k] = 0.5f * (b + d);
        out_imag[rB + k] = 0.5f * (c - a);
    }
    if (j == 0) {                                        // k = 512 (self-mirror)
        const float a = B1r[f][P6(512)], b = B1i[f][P6(512)];
        out_real[rA + 512] = a;
        out_imag[rA + 512] = 0.0f;
        out_real[rB + 512] = b;
        out_imag[rB + 512] = 0.0f;
    }
}

extern "C" void kernel_launch(void* const* d_in, const int* in_sizes, int n_in,
                              void* d_out, int out_size)
{
    const float* x = (const float*)d_in[0];
    float* out = (float*)d_out;
    const int n_rows = in_sizes[0] / NFFT;               // 8192
    float* out_real = out;
    float* out_imag = out + (size_t)n_rows * NOUT;

    const int n_pairs = n_rows / 2;                      // 4096 packed FFTs
    rfft1024_r7_kernel<<<n_pairs / 2, THREADS>>>(x, out_real, out_imag);
}

// round 12
// speedup vs baseline: 3.7495x; 1.0150x over previous
#include <cuda_runtime.h>
#include <cuda_bf16.h>

// RFFT-1024 over 8192 rows -> real[8192][513] ++ imag[8192][513].
// R10: R8 design (1024 = 8 x 8 x 4 x 4, one packed complex FFT per
// 128-thread block, 8 points/thread) with the ex2 layout fixed:
// stride 68 per u-slab, R2 sized 1088 (was colliding/OOB at stride 24).

#define NFFT 1024
#define NOUT 513

__device__ __forceinline__ constexpr int rev3(int i) {
    return ((i & 1) << 2) | (i & 2) | ((i >> 2) & 1);
}

// radix-2 butterflies on register arrays (constant indices after unroll)
#define BF(zr, zi, i0, i1) do {                                         \
    float _tr = zr[i1], _ti = zi[i1];                                   \
    zr[i1] = zr[i0] - _tr;  zi[i1] = zi[i0] - _ti;                      \
    zr[i0] += _tr;          zi[i0] += _ti;                              \
} while (0)

#define BFMI(zr, zi, i0, i1) do {   /* twiddle = -i */                  \
    float _tr = zi[i1], _ti = -zr[i1];                                  \
    zr[i1] = zr[i0] - _tr;  zi[i1] = zi[i0] - _ti;                      \
    zr[i0] += _tr;          zi[i0] += _ti;                              \
} while (0)

#define BFW(zr, zi, i0, i1, wr, wi) do {                                \
    float _tr = (wr) * zr[i1] - (wi) * zi[i1];                          \
    float _ti = (wr) * zi[i1] + (wi) * zr[i1];                          \
    zr[i1] = zr[i0] - _tr;  zi[i1] = zi[i0] - _ti;                      \
    zr[i0] += _tr;          zi[i0] += _ti;                              \
} while (0)

// 8-point DIT FFT: input bit-rev3 wired, natural-order output.
#define FFT8(zr, zi) do {                                               \
    BF(zr, zi, 0, 1); BF(zr, zi, 2, 3); BF(zr, zi, 4, 5); BF(zr, zi, 6, 7); \
    BF(zr, zi, 0, 2); BFMI(zr, zi, 1, 3);                               \
    BF(zr, zi, 4, 6); BFMI(zr, zi, 5, 7);                               \
    BF(zr, zi, 0, 4); BFW(zr, zi, 1, 5,  0.70710678f, -0.70710678f);   \
    BFMI(zr, zi, 2, 6); BFW(zr, zi, 3, 7, -0.70710678f, -0.70710678f); \
} while (0)

// multiply z[k] by W^{k}, W = e^{i ang}, k = 1..7 (recurrence)
#define TW8(zr, zi, ang) do {                                           \
    float _s, _c;  __sincosf((ang), &_s, &_c);                          \
    float _wr = _c, _wi = _s, _cr = _c, _ci = _s;                       \
    _Pragma("unroll")                                                   \
    for (int _k = 1; _k < 8; ++_k) {                                    \
        float _zr = zr[_k], _zi = zi[_k];                               \
        zr[_k] = _cr * _zr - _ci * _zi;                                 \
        zi[_k] = _cr * _zi + _ci * _zr;                                 \
        float _nr = _cr * _wr - _ci * _wi;                              \
        float _ni = _cr * _wi + _ci * _wr;                              \
        _cr = _nr; _ci = _ni;                                           \
    }                                                                   \
} while (0)

// natural-order 4-point DFT: G = DFT4(f)
#define DFT4(Gr, Gi, fr, fi) do {                                       \
    float _e0r = fr[0] + fr[2], _e0i = fi[0] + fi[2];                   \
    float _e1r = fr[0] - fr[2], _e1i = fi[0] - fi[2];                   \
    float _o0r = fr[1] + fr[3], _o0i = fi[1] + fi[3];                   \
    float _o1r = fr[1] - fr[3], _o1i = fi[1] - fi[3];                   \
    Gr[0] = _e0r + _o0r;  Gi[0] = _e0i + _o0i;                          \
    Gr[1] = _e1r + _o1i;  Gi[1] = _e1i - _o1r;                          \
    Gr[2] = _e0r - _o0r;  Gi[2] = _e0i - _o0i;                          \
    Gr[3] = _e1r - _o1i;  Gi[3] = _e1i + _o1r;                          \
} while (0)

__global__ void __launch_bounds__(128, 8)
rfft1024_r10_kernel(const float* __restrict__ x,
                    float* __restrict__ out_real,
                    float* __restrict__ out_imag)
{
    // R1: ex1 [k1][j] stride 130 (reused as ex3: addr b + 64*m2a + 256*u1)
    // R2: ex2 addr = 68*u + 8*m1 + k1  (max 68*15 + 63 = 1083)
    __shared__ float2 R1[1040];
    __shared__ float2 R2[1088];

    const int t   = threadIdx.x;                 // 0..127
    const int fft = blockIdx.x;                  // packed-FFT (row-pair) index

    const float* __restrict__ xa = x + (size_t)(2 * fft) * NFFT;
    const float* __restrict__ xb = xa + NFFT;

    float zr[8], zi[8];

    // ---- stage A: load z[n1] = x[128*n1 + t] (bit-rev wired), FFT8 ----
#pragma unroll
    for (int n1 = 0; n1 < 8; ++n1) {
        const int r = rev3(n1);
        zr[r] = xa[128 * n1 + t];
        zi[r] = xb[128 * n1 + t];
    }
    FFT8(zr, zi);
    TW8(zr, zi, (-6.28318530717958647692f / 1024.0f) * (float)t);   // W1024^{t*k1}

#pragma unroll
    for (int k1 = 0; k1 < 8; ++k1)
        R1[130 * k1 + t] = make_float2(zr[k1], zi[k1]);
    __syncthreads();

    // ---- stage B: FFT8 over j1 for (k1, u) = (t&7, t>>3) ----
    const int k1b = t & 7;
    const int ub  = t >> 3;                      // 0..15
    {
        const int base = 130 * k1b + ub;
#pragma unroll
        for (int j1 = 0; j1 < 8; ++j1) {
            const int r = rev3(j1);
            const float2 v = R1[base + 16 * j1];
            zr[r] = v.x;  zi[r] = v.y;
        }
    }
    FFT8(zr, zi);
    TW8(zr, zi, (-6.28318530717958647692f / 128.0f) * (float)ub);   // W128^{u*m1}

#pragma unroll
    for (int m1 = 0; m1 < 8; ++m1)
        R2[68 * ub + 8 * m1 + k1b] = make_float2(zr[m1], zi[m1]);
    __syncthreads();

    // ---- stage C: DFT4 over u2 + twiddle W16^{u1*m2a}; 2 quads/thread ----
#pragma unroll
    for (int qq = 0; qq < 2; ++qq) {
        const int q3  = t + 128 * qq;            // k1 + 8*m1 + 64*u1
        const int ck1 = q3 & 7;
        const int cm1 = (q3 >> 3) & 7;
        const int cu1 = q3 >> 6;                 // 0..3
        float fr[4], fi[4], Gr[4], Gi[4];
#pragma unroll
        for (int u2 = 0; u2 < 4; ++u2) {
            const float2 v = R2[68 * (cu1 + 4 * u2) + 8 * cm1 + ck1];
            fr[u2] = v.x;  fi[u2] = v.y;
        }
        DFT4(Gr, Gi, fr, fi);
        // exact twiddles W16^{cu1}, W16^{2*cu1}, W16^{3*cu1} via selects
        const float w1r = (cu1 == 0) ? 1.0f : (cu1 == 1) ? 0.92387953f : (cu1 == 2) ? 0.70710678f : 0.38268343f;
        const float w1i = (cu1 == 0) ? 0.0f : (cu1 == 1) ? -0.38268343f : (cu1 == 2) ? -0.70710678f : -0.92387953f;
        const float w2r = (cu1 == 0) ? 1.0f : (cu1 == 1) ? 0.70710678f : (cu1 == 2) ? 0.0f : -0.70710678f;
        const float w2i = (cu1 == 0) ? 0.0f : (cu1 == 1) ? -0.70710678f : (cu1 == 2) ? -1.0f : -0.70710678f;
        const float w3r = (cu1 == 0) ? 1.0f : (cu1 == 1) ? 0.38268343f : (cu1 == 2) ? -0.70710678f : -0.92387953f;
        const float w3i = (cu1 == 0) ? 0.0f : (cu1 == 1) ? -0.92387953f : (cu1 == 2) ? -0.70710678f : 0.38268343f;
        float g1r = w1r * Gr[1] - w1i * Gi[1], g1i = w1r * Gi[1] + w1i * Gr[1];
        float g2r = w2r * Gr[2] - w2i * Gi[2], g2i = w2r * Gi[2] + w2i * Gr[2];
        float g3r = w3r * Gr[3] - w3i * Gi[3], g3i = w3r * Gi[3] + w3i * Gr[3];

        const int b = ck1 + 8 * cm1;             // + 64*m2a below
        R1[b + 256 * cu1]       = make_float2(Gr[0], Gi[0]);
        R1[b + 64 + 256 * cu1]  = make_float2(g1r, g1i);
        R1[b + 128 + 256 * cu1] = make_float2(g2r, g2i);
        R1[b + 192 + 256 * cu1] = make_float2(g3r, g3i);
    }
    __syncthreads();

    // ---- stage D: DFT4 over u1 for mirror-paired bases {t, 256-t};
    //      Z[k] and Z[1024-k] end up thread-local -> fused Hermitian unpack ----
    const int bA = t;
    const int bB = (t == 0) ? 128 : 256 - t;

    float Ar[4], Ai[4], Br[4], Bi[4];
    {
        float hr[4], hi[4];
#pragma unroll
        for (int u1 = 0; u1 < 4; ++u1) {
            const float2 v = R1[bA + 256 * u1];
            hr[u1] = v.x;  hi[u1] = v.y;
        }
        DFT4(Ar, Ai, hr, hi);                    // Ar[q] = Z[bA + 256*q]
#pragma unroll
        for (int u1 = 0; u1 < 4; ++u1) {
            const float2 v = R1[bB + 256 * u1];
            hr[u1] = v.x;  hi[u1] = v.y;
        }
        DFT4(Br, Bi, hr, hi);                    // Br[q] = Z[bB + 256*q]
    }

    // ---- stores: Xa, Xb from (Z[k], Z[1024-k]) pairs ----
    const size_t rA = (size_t)(2 * fft) * NOUT;
    const size_t rB = rA + NOUT;

#define STORE_PAIR(k, ar_, ai_, cr_, ci_) do {                          \
    out_real[rA + (k)] = 0.5f * ((ar_) + (cr_));                        \
    out_imag[rA + (k)] = 0.5f * ((ai_) - (ci_));                        \
    out_real[rB + (k)] = 0.5f * ((ai_) + (ci_));                        \
    out_imag[rB + (k)] = 0.5f * ((cr_) - (ar_));                        \
} while (0)

    if (t > 0) {
        STORE_PAIR(t,        Ar[0], Ai[0], Br[3], Bi[3]);   // Z[t],     Z[1024-t]
        STORE_PAIR(t + 256,  Ar[1], Ai[1], Br[2], Bi[2]);   // Z[t+256], Z[768-t]
        STORE_PAIR(256 - t,  Br[0], Bi[0], Ar[3], Ai[3]);   // Z[256-t], Z[768+t]
        STORE_PAIR(512 - t,  Br[1], Bi[1], Ar[2], Ai[2]);   // Z[512-t], Z[512+t]
    } else {
        STORE_PAIR(0,    Ar[0], Ai[0], Ar[0], Ai[0]);
        STORE_PAIR(256,  Ar[1], Ai[1], Ar[3], Ai[3]);
        STORE_PAIR(512,  Ar[2], Ai[2], Ar[2], Ai[2]);
        STORE_PAIR(128,  Br[0], Bi[0], Br[3], Bi[3]);
        STORE_PAIR(384,  Br[1], Bi[1], Br[2], Bi[2]);
    }
#undef STORE_PAIR
}

extern "C" void kernel_launch(void* const* d_in, const int* in_sizes, int n_in,
                              void* d_out, int out_size)
{
    const float* x = (const float*)d_in[0];
    float* out = (float*)d_out;
    const int n_rows = in_sizes[0] / NFFT;               // 8192
    float* out_real = out;
    float* out_imag = out + (size_t)n_rows * NOUT;

    const int n_pairs = n_rows / 2;                      // 4096 packed FFTs
    rfft1024_r10_kernel<<<n_pairs, 128>>>(x, out_real, out_imag);
}

// round 16
// speedup vs baseline: 3.8065x; 1.0152x over previous
#include <cuda_runtime.h>
#include <cuda_bf16.h>

// RFFT-1024 over 8192 rows -> real[8192][513] ++ imag[8192][513].
// R12: R10 dataflow (1024 = 8 x 8 x 4 x 4, 8 pts/thread, fused Hermitian
// stage D) with: single-wave persistent blocks (1024 blocks x 4 FFTs),
// conflict-free ex2 (stride 72), and depth-3 parallel twiddle powers.

#define NFFT 1024
#define NOUT 513
#define FFTS_PER_BLOCK 4

__device__ __forceinline__ constexpr int rev3(int i) {
    return ((i & 1) << 2) | (i & 2) | ((i >> 2) & 1);
}

#define BF(zr, zi, i0, i1) do {                                         \
    float _tr = zr[i1], _ti = zi[i1];                                   \
    zr[i1] = zr[i0] - _tr;  zi[i1] = zi[i0] - _ti;                      \
    zr[i0] += _tr;          zi[i0] += _ti;                              \
} while (0)

#define BFMI(zr, zi, i0, i1) do {   /* twiddle = -i */                  \
    float _tr = zi[i1], _ti = -zr[i1];                                  \
    zr[i1] = zr[i0] - _tr;  zi[i1] = zi[i0] - _ti;                      \
    zr[i0] += _tr;          zi[i0] += _ti;                              \
} while (0)

#define BFW(zr, zi, i0, i1, wr, wi) do {                                \
    float _tr = (wr) * zr[i1] - (wi) * zi[i1];                          \
    float _ti = (wr) * zi[i1] + (wi) * zr[i1];                          \
    zr[i1] = zr[i0] - _tr;  zi[i1] = zi[i0] - _ti;                      \
    zr[i0] += _tr;          zi[i0] += _ti;                              \
} while (0)

// 8-point DIT FFT: input bit-rev3 wired, natural-order output.
#define FFT8(zr, zi) do {                                               \
    BF(zr, zi, 0, 1); BF(zr, zi, 2, 3); BF(zr, zi, 4, 5); BF(zr, zi, 6, 7); \
    BF(zr, zi, 0, 2); BFMI(zr, zi, 1, 3);                               \
    BF(zr, zi, 4, 6); BFMI(zr, zi, 5, 7);                               \
    BF(zr, zi, 0, 4); BFW(zr, zi, 1, 5,  0.70710678f, -0.70710678f);   \
    BFMI(zr, zi, 2, 6); BFW(zr, zi, 3, 7, -0.70710678f, -0.70710678f); \
} while (0)

#define CMULK(zr, zi, k, wr, wi) do {                                   \
    float _zr = zr[k], _zi = zi[k];                                     \
    zr[k] = (wr) * _zr - (wi) * _zi;                                    \
    zi[k] = (wr) * _zi + (wi) * _zr;                                    \
} while (0)

// multiply z[k] by W^{k}, W = e^{i ang}, k = 1..7.
// Depth-3 power tree; all 7 applications independent (short dep chain).
#define TW8(zr, zi, ang) do {                                           \
    float _s, _c;  __sincosf((ang), &_s, &_c);                          \
    const float w1r = _c, w1i = _s;                                     \
    const float w2r = w1r * w1r - w1i * w1i, w2i = 2.0f * w1r * w1i;    \
    const float w4r = w2r * w2r - w2i * w2i, w4i = 2.0f * w2r * w2i;    \
    const float w3r = w2r * w1r - w2i * w1i, w3i = w2r * w1i + w2i * w1r; \
    const float w5r = w4r * w1r - w4i * w1i, w5i = w4r * w1i + w4i * w1r; \
    const float w6r = w4r * w2r - w4i * w2i, w6i = w4r * w2i + w4i * w2r; \
    const float w7r = w4r * w3r - w4i * w3i, w7i = w4r * w3i + w4i * w3r; \
    CMULK(zr, zi, 1, w1r, w1i);  CMULK(zr, zi, 2, w2r, w2i);            \
    CMULK(zr, zi, 3, w3r, w3i);  CMULK(zr, zi, 4, w4r, w4i);            \
    CMULK(zr, zi, 5, w5r, w5i);  CMULK(zr, zi, 6, w6r, w6i);            \
    CMULK(zr, zi, 7, w7r, w7i);                                         \
} while (0)

// natural-order 4-point DFT: G = DFT4(f)
#define DFT4(Gr, Gi, fr, fi) do {                                       \
    float _e0r = fr[0] + fr[2], _e0i = fi[0] + fi[2];                   \
    float _e1r = fr[0] - fr[2], _e1i = fi[0] - fi[2];                   \
    float _o0r = fr[1] + fr[3], _o0i = fi[1] + fi[3];                   \
    float _o1r = fr[1] - fr[3], _o1i = fi[1] - fi[3];                   \
    Gr[0] = _e0r + _o0r;  Gi[0] = _e0i + _o0i;                          \
    Gr[1] = _e1r + _o1i;  Gi[1] = _e1i - _o1r;                          \
    Gr[2] = _e0r - _o0r;  Gi[2] = _e0i - _o0i;                          \
    Gr[3] = _e1r - _o1i;  Gi[3] = _e1i + _o1r;                          \
} while (0)

__global__ void __launch_bounds__(128, 8)
rfft1024_r12_kernel(const float* __restrict__ x,
                    float* __restrict__ out_real,
                    float* __restrict__ out_imag)
{
    // R1: ex1 [k1][j] stride 130 (reused as ex3: addr b + 64*m2a + 256*u1)
    // R2: ex2 addr = 72*u + 8*m1 + k1  (max 72*15 + 63 = 1143; conflict-free)
    __shared__ float2 R1[1040];
    __shared__ float2 R2[1152];

    const int t = threadIdx.x;                   // 0..127

    for (int it = 0; it < FFTS_PER_BLOCK; ++it) {
        const int fft = blockIdx.x * FFTS_PER_BLOCK + it;

        const float* __restrict__ xa = x + (size_t)(2 * fft) * NFFT;
        const float* __restrict__ xb = xa + NFFT;

        float zr[8], zi[8];

        // ---- stage A: load z[n1] = x[128*n1 + t] (bit-rev wired), FFT8 ----
#pragma unroll
        for (int n1 = 0; n1 < 8; ++n1) {
            const int r = rev3(n1);
            zr[r] = xa[128 * n1 + t];
            zi[r] = xb[128 * n1 + t];
        }
        FFT8(zr, zi);
        TW8(zr, zi, (-6.28318530717958647692f / 1024.0f) * (float)t);

#pragma unroll
        for (int k1 = 0; k1 < 8; ++k1)
            R1[130 * k1 + t] = make_float2(zr[k1], zi[k1]);
        __syncthreads();

        // ---- stage B: FFT8 over j1 for (k1, u) = (t&7, t>>3) ----
        const int k1b = t & 7;
        const int ub  = t >> 3;                  // 0..15
        {
            const int base = 130 * k1b + ub;
#pragma unroll
            for (int j1 = 0; j1 < 8; ++j1) {
                const int r = rev3(j1);
                const float2 v = R1[base + 16 * j1];
                zr[r] = v.x;  zi[r] = v.y;
            }
        }
        FFT8(zr, zi);
        TW8(zr, zi, (-6.28318530717958647692f / 128.0f) * (float)ub);

#pragma unroll
        for (int m1 = 0; m1 < 8; ++m1)
            R2[72 * ub + 8 * m1 + k1b] = make_float2(zr[m1], zi[m1]);
        __syncthreads();

        // ---- stage C: DFT4 over u2 + twiddle W16^{u1*m2a}; 2 quads/thread ----
#pragma unroll
        for (int qq = 0; qq < 2; ++qq) {
            const int q3  = t + 128 * qq;        // k1 + 8*m1 + 64*u1
            const int ck1 = q3 & 7;
            const int cm1 = (q3 >> 3) & 7;
            const int cu1 = q3 >> 6;             // 0..3
            float fr[4], fi[4], Gr[4], Gi[4];
#pragma unroll
            for (int u2 = 0; u2 < 4; ++u2) {
                const float2 v = R2[72 * (cu1 + 4 * u2) + 8 * cm1 + ck1];
                fr[u2] = v.x;  fi[u2] = v.y;
            }
            DFT4(Gr, Gi, fr, fi);
            const float w1r = (cu1 == 0) ? 1.0f : (cu1 == 1) ? 0.92387953f : (cu1 == 2) ? 0.70710678f : 0.38268343f;
            const float w1i = (cu1 == 0) ? 0.0f : (cu1 == 1) ? -0.38268343f : (cu1 == 2) ? -0.70710678f : -0.92387953f;
            const float w2r = (cu1 == 0) ? 1.0f : (cu1 == 1) ? 0.70710678f : (cu1 == 2) ? 0.0f : -0.70710678f;
            const float w2i = (cu1 == 0) ? 0.0f : (cu1 == 1) ? -0.70710678f : (cu1 == 2) ? -1.0f : -0.70710678f;
            const float w3r = (cu1 == 0) ? 1.0f : (cu1 == 1) ? 0.38268343f : (cu1 == 2) ? -0.70710678f : -0.92387953f;
            const float w3i = (cu1 == 0) ? 0.0f : (cu1 == 1) ? -0.92387953f : (cu1 == 2) ? -0.70710678f : 0.38268343f;
            float g1r = w1r * Gr[1] - w1i * Gi[1], g1i = w1r * Gi[1] + w1i * Gr[1];
            float g2r = w2r * Gr[2] - w2i * Gi[2], g2i = w2r * Gi[2] + w2i * Gr[2];
            float g3r = w3r * Gr[3] - w3i * Gi[3], g3i = w3r * Gi[3] + w3i * Gr[3];

            const int b = ck1 + 8 * cm1;         // + 64*m2a below
            R1[b + 256 * cu1]       = make_float2(Gr[0], Gi[0]);
            R1[b + 64 + 256 * cu1]  = make_float2(g1r, g1i);
            R1[b + 128 + 256 * cu1] = make_float2(g2r, g2i);
            R1[b + 192 + 256 * cu1] = make_float2(g3r, g3i);
        }
        __syncthreads();

        // ---- stage D: DFT4 over u1 for mirror bases {t, 256-t} + unpack ----
        const int bA = t;
        const int bB = (t == 0) ? 128 : 256 - t;

        float Ar[4], Ai[4], Br[4], Bi[4];
        {
            float hr[4], hi[4];
#pragma unroll
            for (int u1 = 0; u1 < 4; ++u1) {
                const float2 v = R1[bA + 256 * u1];
                hr[u1] = v.x;  hi[u1] = v.y;
            }
            DFT4(Ar, Ai, hr, hi);                // Ar[q] = Z[bA + 256*q]
#pragma unroll
            for (int u1 = 0; u1 < 4; ++u1) {
                const float2 v = R1[bB + 256 * u1];
                hr[u1] = v.x;  hi[u1] = v.y;
            }
            DFT4(Br, Bi, hr, hi);                // Br[q] = Z[bB + 256*q]
        }

        const size_t rA = (size_t)(2 * fft) * NOUT;
        const size_t rB = rA + NOUT;

#define STORE_PAIR(k, ar_, ai_, cr_, ci_) do {                          \
    out_real[rA + (k)] = 0.5f * ((ar_) + (cr_));                        \
    out_imag[rA + (k)] = 0.5f * ((ai_) - (ci_));                        \
    out_real[rB + (k)] = 0.5f * ((ai_) + (ci_));                        \
    out_imag[rB + (k)] = 0.5f * ((cr_) - (ar_));                        \
} while (0)

        if (t > 0) {
            STORE_PAIR(t,        Ar[0], Ai[0], Br[3], Bi[3]);   // Z[t],     Z[1024-t]
            STORE_PAIR(t + 256,  Ar[1], Ai[1], Br[2], Bi[2]);   // Z[t+256], Z[768-t]
            STORE_PAIR(256 - t,  Br[0], Bi[0], Ar[3], Ai[3]);   // Z[256-t], Z[768+t]
            STORE_PAIR(512 - t,  Br[1], Bi[1], Ar[2], Ai[2]);   // Z[512-t], Z[512+t]
        } else {
            STORE_PAIR(0,    Ar[0], Ai[0], Ar[0], Ai[0]);
            STORE_PAIR(256,  Ar[1], Ai[1], Ar[3], Ai[3]);
            STORE_PAIR(512,  Ar[2], Ai[2], Ar[2], Ai[2]);
            STORE_PAIR(128,  Br[0], Bi[0], Br[3], Bi[3]);
            STORE_PAIR(384,  Br[1], Bi[1], Br[2], Bi[2]);
        }
#undef STORE_PAIR

        // R1 is rewritten by the next iteration's stage A; stage-D reads of
        // all threads must drain first.
        __syncthreads();
    }
}

extern "C" void kernel_launch(void* const* d_in, const int* in_sizes, int n_in,
                              void* d_out, int out_size)
{
    const float* x = (const float*)d_in[0];
    float* out = (float*)d_out;
    const int n_rows = in_sizes[0] / NFFT;               // 8192
    float* out_real = out;
    float* out_imag = out + (size_t)n_rows * NOUT;

    const int n_pairs  = n_rows / 2;                     // 4096 packed FFTs
    const int n_blocks = n_pairs / FFTS_PER_BLOCK;       // 1024 -> single wave
    rfft1024_r12_kernel<<<n_blocks, 128>>>(x, out_real, out_imag);
}